// round 13
// baseline (speedup 1.0000x reference)
#include <cuda_runtime.h>
#include <cstdint>
#include <cuda_fp16.h>
#include <mma.h>

using namespace nvcuda;

// Problem constants: B=4, L=1024, D=1024, H=16
// Half scratch buffers.
__device__ __half h_x[4194304];      // x [4096,1024]
__device__ __half h_wk[16777216];    // Wk [16,1024,1024]
__device__ __half h_wqT[16777216];   // Wq^T per head [16][i][d]
__device__ __half h_wvT[16777216];   // Wv^T per head [16][e][d]
__device__ __half h_wog[16777216];   // gathered Wo: [16][d][o]
__device__ __half h_G[16777216];     // G_h = Wq_h^T Wk_h
__device__ __half h_U[16777216];     // U_h = Wv_h^T Wo'_h
__device__ __half h_P[67108864];     // P = x @ G ; later reused as float[8][4M] split-K partials
__device__ __half h_Y[67108864];     // Y = x_b @ U_h  [(h*4+b)][1024][1024]
__device__ __half h_attn[67108864];  // attn half copy [(b*16+h)][1024][1024]

// ---------------------------------------------------------------------------
constexpr int BM = 128, BN = 128, BK = 64;
constexpr int STG = 3;
constexpr int LDA_S = BK + 8;            // 72 halves
constexpr int LDB_S = BN + 8;            // 136 halves
constexpr int A_TILE = BM * LDA_S;
constexpr int BT_TILE = BN * LDA_S;
constexpr int STAGE_H = A_TILE + BT_TILE;           // 18432 halves
constexpr int SMEM_BYTES = STG * STAGE_H * 2;       // 110592 B
constexpr long long M1 = 1024LL * 1024;
constexpr long long M4 = 4096LL * 1024;

__device__ __forceinline__ void cp16(const void* smem_dst, const void* src) {
    unsigned dst = (unsigned)__cvta_generic_to_shared(smem_dst);
    asm volatile("cp.async.cg.shared.global [%0], [%1], 16;\n" :: "r"(dst), "l"(src));
}
#define CP_COMMIT() asm volatile("cp.async.commit_group;" ::: "memory")
#define CP_WAIT(n)  asm volatile("cp.async.wait_group %0;" :: "n"(n) : "memory")

// ---------------------------------------------------------------------------
// fp16 wmma GEMM body, fp32 accumulate. 256 threads, 8 warps, 64x32 per warp.
//   BT   : C = A @ B^T (B stored [N,K]); else C = A @ B (B stored [K,N]).
//   SEGK : segmented-K (K split into 1024-row head segments, both strides 1024).
//   HOUT : half output via smem staging; else direct fp32 wmma store.
// A, Bp, Cc are fully batch-offset by the caller.
// ---------------------------------------------------------------------------
template <bool BT, bool SEGK, bool HOUT>
__device__ __forceinline__ void gemm_body(
    const __half* __restrict__ A, const __half* __restrict__ Bp,
    void* __restrict__ Cc, int lda, int ldb, int ldc, int K, __half* smem)
{
    __half* Asm = smem;
    __half* Bsm = smem + STG * A_TILE;

    const int tid = threadIdx.x;
    const int warpId = tid >> 5;
    const int lane = tid & 31;
    const int rowBase = blockIdx.y * BM;
    const int colBase = blockIdx.x * BN;
    const int wRow = (warpId >> 2) * 64;
    const int wCol = (warpId & 3) * 32;

    wmma::fragment<wmma::accumulator, 16, 16, 16, float> acc[4][2];
#pragma unroll
    for (int i = 0; i < 4; i++)
#pragma unroll
        for (int j = 0; j < 2; j++) wmma::fill_fragment(acc[i][j], 0.0f);

    const int T = K >> 6;

    auto a_base = [&](int kt) -> const __half* {
        const int k0 = kt << 6;
        if constexpr (SEGK) return A + ((long long)(k0 >> 10) << 20) + (k0 & 1023);
        else return A + k0;
    };
    auto b_base = [&](int kt) -> const __half* {
        const int k0 = kt << 6;
        if constexpr (SEGK) return Bp + ((long long)(k0 >> 10) << 22) + (long long)(k0 & 1023) * 1024;
        else return Bp + (BT ? k0 : (long long)k0 * ldb);
    };
    const int rs_a = SEGK ? 1024 : lda;
    const int rs_b = SEGK ? 1024 : ldb;

    auto issueA = [&](int kt) {
        const int buf = kt % STG;
        const __half* At = a_base(kt);
#pragma unroll
        for (int i = 0; i < 4; i++) {
            const int c = tid + i * 256;
            const int r = c >> 3;
            const int col = (c & 7) << 3;
            cp16(&Asm[(buf * BM + r) * LDA_S + col],
                 &At[(long long)(rowBase + r) * rs_a + col]);
        }
    };
    // B prefetch in two halves (h = 0 or 1), 2 cp16 each.
    auto issueB = [&](int kt, int half) {
        const int buf = kt % STG;
        const __half* Bt = b_base(kt);
        if constexpr (BT) {
#pragma unroll
            for (int i = 0; i < 2; i++) {
                const int c = tid + (half * 2 + i) * 256;
                const int r = c >> 3;
                const int col = (c & 7) << 3;
                cp16(&Bsm[(buf * BN + r) * LDA_S + col],
                     &Bt[(long long)(colBase + r) * rs_b + col]);
            }
        } else {
#pragma unroll
            for (int i = 0; i < 2; i++) {
                const int c = tid + (half * 2 + i) * 256;
                const int r = c >> 4;
                const int col = (c & 15) << 3;
                cp16(&Bsm[(buf * BK + r) * LDB_S + col],
                     &Bt[(long long)r * rs_b + colBase + col]);
            }
        }
    };

    // Reordered kk step: B fragments first, then per-i {load A; 2 MMAs}.
    auto compute = [&](const __half* Ab, const __half* Bb, int kk) {
        if constexpr (BT) {
            wmma::fragment<wmma::matrix_b, 16, 16, 16, __half, wmma::col_major> bf[2];
#pragma unroll
            for (int j = 0; j < 2; j++)
                wmma::load_matrix_sync(bf[j], &Bb[(wCol + j * 16) * LDA_S + kk], LDA_S);
#pragma unroll
            for (int i = 0; i < 4; i++) {
                wmma::fragment<wmma::matrix_a, 16, 16, 16, __half, wmma::row_major> af;
                wmma::load_matrix_sync(af, &Ab[(wRow + i * 16) * LDA_S + kk], LDA_S);
                wmma::mma_sync(acc[i][0], af, bf[0], acc[i][0]);
                wmma::mma_sync(acc[i][1], af, bf[1], acc[i][1]);
            }
        } else {
            wmma::fragment<wmma::matrix_b, 16, 16, 16, __half, wmma::row_major> bf[2];
#pragma unroll
            for (int j = 0; j < 2; j++)
                wmma::load_matrix_sync(bf[j], &Bb[kk * LDB_S + wCol + j * 16], LDB_S);
#pragma unroll
            for (int i = 0; i < 4; i++) {
                wmma::fragment<wmma::matrix_a, 16, 16, 16, __half, wmma::row_major> af;
                wmma::load_matrix_sync(af, &Ab[(wRow + i * 16) * LDA_S + kk], LDA_S);
                wmma::mma_sync(acc[i][0], af, bf[0], acc[i][0]);
                wmma::mma_sync(acc[i][1], af, bf[1], acc[i][1]);
            }
        }
    };

#pragma unroll
    for (int s = 0; s < STG - 1; s++) { issueA(s); issueB(s, 0); issueB(s, 1); CP_COMMIT(); }

    for (int kt = 0; kt < T; kt++) {
        // One barrier per tile: after wait+barrier, tile kt is visible to all and
        // all warps finished compute(kt-1) so its stage can be overwritten.
        CP_WAIT(STG - 2);
        __syncthreads();

        const int buf = kt % STG;
        const __half* Ab = &Asm[buf * BM * LDA_S];
        const __half* Bb = BT ? &Bsm[buf * BN * LDA_S] : &Bsm[buf * BK * LDB_S];

        // Spread the prefetch evenly: A after kk=0, B halves after kk=16 / kk=32.
        // Still exactly one commit group per tile.
        const int pf = kt + STG - 1;
        compute(Ab, Bb, 0);
        if (pf < T) issueA(pf);
        compute(Ab, Bb, 16);
        if (pf < T) issueB(pf, 0);
        compute(Ab, Bb, 32);
        if (pf < T) issueB(pf, 1);
        CP_COMMIT();
        compute(Ab, Bb, 48);
    }

    if constexpr (!HOUT) {
        float* C = (float*)Cc;
#pragma unroll
        for (int i = 0; i < 4; i++)
#pragma unroll
            for (int j = 0; j < 2; j++) {
                float* cp = &C[(long long)(rowBase + wRow + i * 16) * ldc + colBase + wCol + j * 16];
                wmma::store_matrix_sync(cp, acc[i][j], ldc, wmma::mem_row_major);
            }
    } else {
        __syncthreads();
        float* patch = (float*)smem + warpId * 320;     // 16 x 20
        const int pr = lane & 15;
        const int ps = (lane >> 4) << 3;
#pragma unroll
        for (int i = 0; i < 4; i++)
#pragma unroll
            for (int j = 0; j < 2; j++) {
                wmma::store_matrix_sync(patch, acc[i][j], 20, wmma::mem_row_major);
                __syncwarp();
                union { uint4 u; __half2 hh[4]; } pk;
#pragma unroll
                for (int t = 0; t < 4; t++)
                    pk.hh[t] = __floats2half2_rn(patch[pr * 20 + ps + t * 2],
                                                 patch[pr * 20 + ps + t * 2 + 1]);
                const int row = rowBase + wRow + i * 16 + pr;
                const int col = colBase + wCol + j * 16;
                __half* dst = (__half*)Cc + (long long)row * ldc + col + ps;
                *reinterpret_cast<uint4*>(dst) = pk.u;
                __syncwarp();
            }
    }
}

// ---------------------------------------------------------------------------
// Merged G+U kernel: z<16 -> G_h = Wq_h^T @ Wk_h ; z>=16 -> U_h = Wv_h^T @ Wo'_h
// ---------------------------------------------------------------------------
__global__ __launch_bounds__(256, 2) void gemm_gu(
    const __half* __restrict__ wqT, const __half* __restrict__ wkh,
    const __half* __restrict__ wvT, const __half* __restrict__ wog,
    __half* __restrict__ G, __half* __restrict__ U)
{
    extern __shared__ __half smem[];
    const int z = blockIdx.z;
    const __half *A, *B;
    __half* C;
    if (z < 16) { A = wqT + (long long)z * M1; B = wkh + (long long)z * M1; C = G + (long long)z * M1; }
    else { const int y = z - 16; A = wvT + (long long)y * M1; B = wog + (long long)y * M1; C = U + (long long)y * M1; }
    gemm_body<false, false, true>(A, B, C, 1024, 1024, 1024, 1024, smem);
}

// ---------------------------------------------------------------------------
// P = x @ G_h  (per head z)
// ---------------------------------------------------------------------------
__global__ __launch_bounds__(256, 2) void gemm_p(
    const __half* __restrict__ xh, const __half* __restrict__ G, __half* __restrict__ P)
{
    extern __shared__ __half smem[];
    const int z = blockIdx.z;
    gemm_body<false, false, true>(xh, G + (long long)z * M1, P + (long long)z * M4,
                                  1024, 1024, 1024, 1024, smem);
}

// ---------------------------------------------------------------------------
// Merged logits+Y kernel:
//   z<64 : logits = P_{h,b} @ x_b^T (BT, fp32 store at plane zp=(z&3)*16+(z>>2))
//   z>=64: Y_{h,b} = x_b @ U_h (NN, half out), y=z-64, y=h*4+b
// ---------------------------------------------------------------------------
__global__ __launch_bounds__(256, 2) void gemm_ly(
    const __half* __restrict__ Ph, const __half* __restrict__ xh,
    const __half* __restrict__ Uh, float* __restrict__ attn, __half* __restrict__ Yh)
{
    extern __shared__ __half smem[];
    const int z = blockIdx.z;
    if (z < 64) {
        const int zp = (z & 3) * 16 + (z >> 2);
        gemm_body<true, false, false>(Ph + (long long)z * M1, xh + (long long)(z & 3) * M1,
                                      attn + (long long)zp * M1, 1024, 1024, 1024, 1024, smem);
    } else {
        const int y = z - 64;
        gemm_body<false, false, true>(xh + (long long)(y & 3) * M1, Uh + (long long)(y >> 2) * M1,
                                      Yh + (long long)y * M1, 1024, 1024, 1024, 1024, smem);
    }
}

// ---------------------------------------------------------------------------
// Split-K final (8 chunks): z = c*4+b, c=z>>2 covers heads {2c, 2c+1}, b=z&3.
//   partial[z] = attn_{heads 2c..2c+1, b} @ Y_{...}  (segmented K=2048)
// ---------------------------------------------------------------------------
__global__ __launch_bounds__(256, 2) void gemm_final(
    const __half* __restrict__ ah, const __half* __restrict__ Yh, float* __restrict__ partial)
{
    extern __shared__ __half smem[];
    const int z = blockIdx.z;
    const __half* A = ah + (long long)(z & 3) * (16 * M1) + (long long)(z >> 2) * (2 * M1);
    const __half* B = Yh + (long long)(z & 3) * M1 + (long long)(z >> 2) * (8 * M1);
    gemm_body<false, true, false>(A, B, partial + (long long)z * M1, 1024, 1024, 1024, 2048, smem);
}

// ---------------------------------------------------------------------------
// Fused prep: one launch, 5 segments (256 threads).
// ---------------------------------------------------------------------------
__global__ __launch_bounds__(256) void prep_kernel(
    const float* __restrict__ x,  const float* __restrict__ Wq,
    const float* __restrict__ Wk, const float* __restrict__ Wv,
    const float* __restrict__ Wo,
    __half* __restrict__ xh, __half* __restrict__ wqT,
    __half* __restrict__ wkh, __half* __restrict__ wvT,
    __half* __restrict__ wog)
{
    const int blk = blockIdx.x;
    const int t = threadIdx.x;

    if (blk < 20480) {
        const float4* src; __half2* dst; int idx;
        if (blk < 4096) { src = (const float4*)x;  dst = (__half2*)xh;  idx = blk * 256 + t; }
        else            { src = (const float4*)Wk; dst = (__half2*)wkh; idx = (blk - 4096) * 256 + t; }
        const float4 v = src[idx];
        dst[2 * idx]     = __floats2half2_rn(v.x, v.y);
        dst[2 * idx + 1] = __floats2half2_rn(v.z, v.w);
    } else if (blk < 53248) {
        const float* src; __half* dst; int ti;
        if (blk < 36864) { src = Wq; dst = wqT; ti = blk - 20480; }
        else             { src = Wv; dst = wvT; ti = blk - 36864; }
        const int zh = ti >> 10;
        const int by = ((ti >> 5) & 31) * 32;
        const int bx = (ti & 31) * 32;
        const float* s = src + (long long)zh * 1048576;
        __half* d = dst + (long long)zh * 1048576;
        __shared__ float tt[32][33];
        const int tx = t & 31, ty = t >> 5;
#pragma unroll
        for (int i = 0; i < 4; i++)
            tt[ty + i * 8][tx] = s[(long long)(by + ty + i * 8) * 1024 + bx + tx];
        __syncthreads();
#pragma unroll
        for (int i = 0; i < 4; i++)
            d[(long long)(bx + ty + i * 8) * 1024 + by + tx] =
                __float2half_rn(tt[tx][ty + i * 8]);
    } else {
        const int idx = (blk - 53248) * 256 + t;
        const int o4 = idx & 255;
        const int dd = (idx >> 8) & 1023;
        const int h  = idx >> 18;
        const int srcRow = ((dd >> 6) * 16 + h) * 64 + (dd & 63);
        const float4 v = ((const float4*)Wo)[(long long)srcRow * 256 + o4];
        __half2* dst = (__half2*)wog;
        dst[2 * idx]     = __floats2half2_rn(v.x, v.y);
        dst[2 * idx + 1] = __floats2half2_rn(v.z, v.w);
    }
}

// ---------------------------------------------------------------------------
// In-place masked softmax (vectorized); also emits half copy for the final GEMM.
// ---------------------------------------------------------------------------
__global__ __launch_bounds__(256) void softmax_kernel(
    float* __restrict__ attn, __half* __restrict__ attnh, const float* __restrict__ mask)
{
    const int row = blockIdx.x;          // 0 .. 65535
    const int b = row >> 14;
    const int l = row & 1023;
    float4* p4 = (float4*)(attn + (long long)row * 1024);
    __half2* ph2 = (__half2*)(attnh + (long long)row * 1024);
    const float4* m4 = (const float4*)(mask + ((long long)(b << 10) + l) * 1024);

    const int tid = threadIdx.x;
    float4 v = p4[tid];
    const float4 m = m4[tid];
    v.x = v.x * 0.03125f - 1e9f * m.x;
    v.y = v.y * 0.03125f - 1e9f * m.y;
    v.z = v.z * 0.03125f - 1e9f * m.z;
    v.w = v.w * 0.03125f - 1e9f * m.w;
    float mx = fmaxf(fmaxf(v.x, v.y), fmaxf(v.z, v.w));

    __shared__ float red[8];
#pragma unroll
    for (int o = 16; o; o >>= 1) mx = fmaxf(mx, __shfl_xor_sync(0xffffffffu, mx, o));
    if ((tid & 31) == 0) red[tid >> 5] = mx;
    __syncthreads();
    mx = red[0];
#pragma unroll
    for (int w = 1; w < 8; w++) mx = fmaxf(mx, red[w]);
    __syncthreads();

    v.x = __expf(v.x - mx);
    v.y = __expf(v.y - mx);
    v.z = __expf(v.z - mx);
    v.w = __expf(v.w - mx);
    float s = v.x + v.y + v.z + v.w;
#pragma unroll
    for (int o = 16; o; o >>= 1) s += __shfl_xor_sync(0xffffffffu, s, o);
    if ((tid & 31) == 0) red[tid >> 5] = s;
    __syncthreads();
    s = red[0];
#pragma unroll
    for (int w = 1; w < 8; w++) s += red[w];
    const float inv = 1.0f / s;

    v.x *= inv; v.y *= inv; v.z *= inv; v.w *= inv;
    p4[tid] = v;
    ph2[2 * tid]     = __floats2half2_rn(v.x, v.y);
    ph2[2 * tid + 1] = __floats2half2_rn(v.z, v.w);
}

// ---------------------------------------------------------------------------
// Split-K reduce: out[i] = sum of 8 partials (each 4M floats).
// ---------------------------------------------------------------------------
__global__ __launch_bounds__(256) void reduce8_kernel(
    const float4* __restrict__ part, float4* __restrict__ out)
{
    const int i = blockIdx.x * 256 + threadIdx.x;   // < 1M float4
    float4 a = part[i];
#pragma unroll
    for (int c = 1; c < 8; c++) {
        const float4 b = part[i + c * 1048576];
        a.x += b.x; a.y += b.y; a.z += b.z; a.w += b.w;
    }
    out[i] = a;
}

// ---------------------------------------------------------------------------
extern "C" void kernel_launch(void* const* d_in, const int* in_sizes, int n_in,
                              void* d_out, int out_size)
{
    const float* x    = (const float*)d_in[0];
    const float* mask = (const float*)d_in[1];
    const float* Wq   = (const float*)d_in[2];
    const float* Wk   = (const float*)d_in[3];
    const float* Wv   = (const float*)d_in[4];
    const float* Wo   = (const float*)d_in[5];
    float* out  = (float*)d_out;
    float* attn = out + 4LL * 1024 * 1024;

    __half *xh, *wkh, *wqT, *wvT, *wog, *Gh, *Uh, *Ph, *Yh, *ah;
    cudaGetSymbolAddress((void**)&xh,  h_x);
    cudaGetSymbolAddress((void**)&wkh, h_wk);
    cudaGetSymbolAddress((void**)&wqT, h_wqT);
    cudaGetSymbolAddress((void**)&wvT, h_wvT);
    cudaGetSymbolAddress((void**)&wog, h_wog);
    cudaGetSymbolAddress((void**)&Gh,  h_G);
    cudaGetSymbolAddress((void**)&Uh,  h_U);
    cudaGetSymbolAddress((void**)&Ph,  h_P);
    cudaGetSymbolAddress((void**)&Yh,  h_Y);
    cudaGetSymbolAddress((void**)&ah,  h_attn);
    float* partial = (float*)Ph;   // reuse h_P after logits GEMM (exactly 128 MB)

    cudaFuncSetAttribute((const void*)gemm_gu,
                         cudaFuncAttributeMaxDynamicSharedMemorySize, SMEM_BYTES);
    cudaFuncSetAttribute((const void*)gemm_p,
                         cudaFuncAttributeMaxDynamicSharedMemorySize, SMEM_BYTES);
    cudaFuncSetAttribute((const void*)gemm_ly,
                         cudaFuncAttributeMaxDynamicSharedMemorySize, SMEM_BYTES);
    cudaFuncSetAttribute((const void*)gemm_final,
                         cudaFuncAttributeMaxDynamicSharedMemorySize, SMEM_BYTES);

    const dim3 blk(256);

    // 0) fused prep (x, Wk convert; Wq, Wv transpose; Wo gather)
    prep_kernel<<<69632, 256>>>(x, Wq, Wk, Wv, Wo, xh, wqT, wkh, wvT, wog);

    // 1) merged G+U  (z 0..31)
    gemm_gu<<<dim3(8, 8, 32), blk, SMEM_BYTES>>>(wqT, wkh, wvT, wog, Gh, Uh);

    // 2) P = x @ G_h  (z 0..15)
    gemm_p<<<dim3(8, 32, 16), blk, SMEM_BYTES>>>(xh, Gh, Ph);

    // 3) merged logits (z 0..63) + Y (z 64..127)
    gemm_ly<<<dim3(8, 8, 128), blk, SMEM_BYTES>>>(Ph, xh, Uh, attn, Yh);

    // 4) masked softmax in place (scale 1/32) + half copy
    softmax_kernel<<<65536, 256>>>(attn, ah, mask);

    // 5) split-K final, 8 chunks (z 0..31)
    gemm_final<<<dim3(8, 8, 32), blk, SMEM_BYTES>>>(ah, Yh, partial);

    // 6) reduce partials -> out
    reduce8_kernel<<<4096, 256>>>((const float4*)partial, (float4*)out);
}

// round 14
// speedup vs baseline: 1.0072x; 1.0072x over previous
#include <cuda_runtime.h>
#include <cstdint>
#include <cuda_fp16.h>
#include <mma.h>

using namespace nvcuda;

// Problem constants: B=4, L=1024, D=1024, H=16
// Half scratch buffers.
__device__ __half h_x[4194304];      // x [4096,1024]
__device__ __half h_wk[16777216];    // Wk [16,1024,1024]
__device__ __half h_wqT[16777216];   // Wq^T per head [16][i][d]
__device__ __half h_wvT[16777216];   // Wv^T per head [16][e][d]
__device__ __half h_wog[16777216];   // gathered Wo: [16][d][o]
__device__ __half h_G[16777216];     // G_h = Wq_h^T Wk_h
__device__ __half h_U[16777216];     // U_h = Wv_h^T Wo'_h
__device__ __half h_P[67108864];     // P = x @ G ; later reused as float[8][4M] split-K partials
__device__ __half h_Y[67108864];     // Y = x_b @ U_h  [(h*4+b)][1024][1024]
__device__ __half h_attn[67108864];  // attn half copy [(b*16+h)][1024][1024]

// ---------------------------------------------------------------------------
constexpr int BM = 128, BN = 128, BK = 64;
constexpr int STG = 3;
constexpr int LDA_S = BK + 8;            // 72 halves
constexpr int LDB_S = BN + 8;            // 136 halves
constexpr int A_TILE = BM * LDA_S;
constexpr int BT_TILE = BN * LDA_S;
constexpr int STAGE_H = A_TILE + BT_TILE;           // 18432 halves
constexpr int SMEM_BYTES = STG * STAGE_H * 2;       // 110592 B
constexpr long long M1 = 1024LL * 1024;
constexpr long long M4 = 4096LL * 1024;

__device__ __forceinline__ void cp16(const void* smem_dst, const void* src) {
    unsigned dst = (unsigned)__cvta_generic_to_shared(smem_dst);
    asm volatile("cp.async.cg.shared.global [%0], [%1], 16;\n" :: "r"(dst), "l"(src));
}
#define CP_COMMIT() asm volatile("cp.async.commit_group;" ::: "memory")
#define CP_WAIT(n)  asm volatile("cp.async.wait_group %0;" :: "n"(n) : "memory")

// ---------------------------------------------------------------------------
// fp16 wmma GEMM body, fp32 accumulate. 256 threads, 8 warps, 64x32 per warp.
//   BT   : C = A @ B^T (B stored [N,K]); else C = A @ B (B stored [K,N]).
//   SEGK : segmented-K (K split into 1024-row head segments, both strides 1024).
//   HOUT : half output via smem staging; else direct fp32 wmma store.
// A, Bp, Cc are fully batch-offset by the caller.
// ---------------------------------------------------------------------------
template <bool BT, bool SEGK, bool HOUT>
__device__ __forceinline__ void gemm_body(
    const __half* __restrict__ A, const __half* __restrict__ Bp,
    void* __restrict__ Cc, int lda, int ldb, int ldc, int K, __half* smem)
{
    __half* Asm = smem;
    __half* Bsm = smem + STG * A_TILE;

    const int tid = threadIdx.x;
    const int warpId = tid >> 5;
    const int lane = tid & 31;
    const int rowBase = blockIdx.y * BM;
    const int colBase = blockIdx.x * BN;
    const int wRow = (warpId >> 2) * 64;
    const int wCol = (warpId & 3) * 32;

    wmma::fragment<wmma::accumulator, 16, 16, 16, float> acc[4][2];
#pragma unroll
    for (int i = 0; i < 4; i++)
#pragma unroll
        for (int j = 0; j < 2; j++) wmma::fill_fragment(acc[i][j], 0.0f);

    const int T = K >> 6;

    auto a_base = [&](int kt) -> const __half* {
        const int k0 = kt << 6;
        if constexpr (SEGK) return A + ((long long)(k0 >> 10) << 20) + (k0 & 1023);
        else return A + k0;
    };
    auto b_base = [&](int kt) -> const __half* {
        const int k0 = kt << 6;
        if constexpr (SEGK) return Bp + ((long long)(k0 >> 10) << 22) + (long long)(k0 & 1023) * 1024;
        else return Bp + (BT ? k0 : (long long)k0 * ldb);
    };
    const int rs_a = SEGK ? 1024 : lda;
    const int rs_b = SEGK ? 1024 : ldb;

    auto issueA = [&](int kt) {
        const int buf = kt % STG;
        const __half* At = a_base(kt);
#pragma unroll
        for (int i = 0; i < 4; i++) {
            const int c = tid + i * 256;
            const int r = c >> 3;
            const int col = (c & 7) << 3;
            cp16(&Asm[(buf * BM + r) * LDA_S + col],
                 &At[(long long)(rowBase + r) * rs_a + col]);
        }
    };
    auto issueB = [&](int kt) {
        const int buf = kt % STG;
        const __half* Bt = b_base(kt);
        if constexpr (BT) {
#pragma unroll
            for (int i = 0; i < 4; i++) {
                const int c = tid + i * 256;
                const int r = c >> 3;
                const int col = (c & 7) << 3;
                cp16(&Bsm[(buf * BN + r) * LDA_S + col],
                     &Bt[(long long)(colBase + r) * rs_b + col]);
            }
        } else {
#pragma unroll
            for (int i = 0; i < 4; i++) {
                const int c = tid + i * 256;
                const int r = c >> 4;
                const int col = (c & 15) << 3;
                cp16(&Bsm[(buf * BK + r) * LDB_S + col],
                     &Bt[(long long)r * rs_b + colBase + col]);
            }
        }
    };

    // Reordered kk step: B fragments first, then per-i {load A; 2 MMAs}.
    auto compute = [&](const __half* Ab, const __half* Bb, int kk) {
        if constexpr (BT) {
            wmma::fragment<wmma::matrix_b, 16, 16, 16, __half, wmma::col_major> bf[2];
#pragma unroll
            for (int j = 0; j < 2; j++)
                wmma::load_matrix_sync(bf[j], &Bb[(wCol + j * 16) * LDA_S + kk], LDA_S);
#pragma unroll
            for (int i = 0; i < 4; i++) {
                wmma::fragment<wmma::matrix_a, 16, 16, 16, __half, wmma::row_major> af;
                wmma::load_matrix_sync(af, &Ab[(wRow + i * 16) * LDA_S + kk], LDA_S);
                wmma::mma_sync(acc[i][0], af, bf[0], acc[i][0]);
                wmma::mma_sync(acc[i][1], af, bf[1], acc[i][1]);
            }
        } else {
            wmma::fragment<wmma::matrix_b, 16, 16, 16, __half, wmma::row_major> bf[2];
#pragma unroll
            for (int j = 0; j < 2; j++)
                wmma::load_matrix_sync(bf[j], &Bb[kk * LDB_S + wCol + j * 16], LDB_S);
#pragma unroll
            for (int i = 0; i < 4; i++) {
                wmma::fragment<wmma::matrix_a, 16, 16, 16, __half, wmma::row_major> af;
                wmma::load_matrix_sync(af, &Ab[(wRow + i * 16) * LDA_S + kk], LDA_S);
                wmma::mma_sync(acc[i][0], af, bf[0], acc[i][0]);
                wmma::mma_sync(acc[i][1], af, bf[1], acc[i][1]);
            }
        }
    };

#pragma unroll
    for (int s = 0; s < STG - 1; s++) { issueA(s); issueB(s); CP_COMMIT(); }

    for (int kt = 0; kt < T; kt++) {
        // One barrier per tile: after wait+barrier, tile kt is visible to all and
        // all warps finished compute(kt-1) so its stage can be overwritten.
        CP_WAIT(STG - 2);
        __syncthreads();

        const int buf = kt % STG;
        const __half* Ab = &Asm[buf * BM * LDA_S];
        const __half* Bb = BT ? &Bsm[buf * BN * LDA_S] : &Bsm[buf * BK * LDB_S];

        // Spread the prefetch: A burst after kk=0, B burst after kk=32 — each
        // burst heads a 2-step compute window. One commit group per tile.
        const int pf = kt + STG - 1;
        compute(Ab, Bb, 0);
        if (pf < T) issueA(pf);
        compute(Ab, Bb, 16);
        compute(Ab, Bb, 32);
        if (pf < T) issueB(pf);
        CP_COMMIT();
        compute(Ab, Bb, 48);
    }

    if constexpr (!HOUT) {
        float* C = (float*)Cc;
#pragma unroll
        for (int i = 0; i < 4; i++)
#pragma unroll
            for (int j = 0; j < 2; j++) {
                float* cp = &C[(long long)(rowBase + wRow + i * 16) * ldc + colBase + wCol + j * 16];
                wmma::store_matrix_sync(cp, acc[i][j], ldc, wmma::mem_row_major);
            }
    } else {
        __syncthreads();
        float* patch = (float*)smem + warpId * 320;     // 16 x 20
        const int pr = lane & 15;
        const int ps = (lane >> 4) << 3;
#pragma unroll
        for (int i = 0; i < 4; i++)
#pragma unroll
            for (int j = 0; j < 2; j++) {
                wmma::store_matrix_sync(patch, acc[i][j], 20, wmma::mem_row_major);
                __syncwarp();
                union { uint4 u; __half2 hh[4]; } pk;
#pragma unroll
                for (int t = 0; t < 4; t++)
                    pk.hh[t] = __floats2half2_rn(patch[pr * 20 + ps + t * 2],
                                                 patch[pr * 20 + ps + t * 2 + 1]);
                const int row = rowBase + wRow + i * 16 + pr;
                const int col = colBase + wCol + j * 16;
                __half* dst = (__half*)Cc + (long long)row * ldc + col + ps;
                *reinterpret_cast<uint4*>(dst) = pk.u;
                __syncwarp();
            }
    }
}

// ---------------------------------------------------------------------------
// Merged G+U kernel: z<16 -> G_h = Wq_h^T @ Wk_h ; z>=16 -> U_h = Wv_h^T @ Wo'_h
// ---------------------------------------------------------------------------
__global__ __launch_bounds__(256, 2) void gemm_gu(
    const __half* __restrict__ wqT, const __half* __restrict__ wkh,
    const __half* __restrict__ wvT, const __half* __restrict__ wog,
    __half* __restrict__ G, __half* __restrict__ U)
{
    extern __shared__ __half smem[];
    const int z = blockIdx.z;
    const __half *A, *B;
    __half* C;
    if (z < 16) { A = wqT + (long long)z * M1; B = wkh + (long long)z * M1; C = G + (long long)z * M1; }
    else { const int y = z - 16; A = wvT + (long long)y * M1; B = wog + (long long)y * M1; C = U + (long long)y * M1; }
    gemm_body<false, false, true>(A, B, C, 1024, 1024, 1024, 1024, smem);
}

// ---------------------------------------------------------------------------
// P = x @ G_h  (per head z)
// ---------------------------------------------------------------------------
__global__ __launch_bounds__(256, 2) void gemm_p(
    const __half* __restrict__ xh, const __half* __restrict__ G, __half* __restrict__ P)
{
    extern __shared__ __half smem[];
    const int z = blockIdx.z;
    gemm_body<false, false, true>(xh, G + (long long)z * M1, P + (long long)z * M4,
                                  1024, 1024, 1024, 1024, smem);
}

// ---------------------------------------------------------------------------
// Merged logits+Y kernel:
//   z<64 : logits = P_{h,b} @ x_b^T (BT, fp32 store at plane zp=(z&3)*16+(z>>2))
//   z>=64: Y_{h,b} = x_b @ U_h (NN, half out), y=z-64, y=h*4+b
// ---------------------------------------------------------------------------
__global__ __launch_bounds__(256, 2) void gemm_ly(
    const __half* __restrict__ Ph, const __half* __restrict__ xh,
    const __half* __restrict__ Uh, float* __restrict__ attn, __half* __restrict__ Yh)
{
    extern __shared__ __half smem[];
    const int z = blockIdx.z;
    if (z < 64) {
        const int zp = (z & 3) * 16 + (z >> 2);
        gemm_body<true, false, false>(Ph + (long long)z * M1, xh + (long long)(z & 3) * M1,
                                      attn + (long long)zp * M1, 1024, 1024, 1024, 1024, smem);
    } else {
        const int y = z - 64;
        gemm_body<false, false, true>(xh + (long long)(y & 3) * M1, Uh + (long long)(y >> 2) * M1,
                                      Yh + (long long)y * M1, 1024, 1024, 1024, 1024, smem);
    }
}

// ---------------------------------------------------------------------------
// Split-K final (8 chunks): z = c*4+b, c=z>>2 covers heads {2c, 2c+1}, b=z&3.
//   partial[z] = attn_{heads 2c..2c+1, b} @ Y_{...}  (segmented K=2048)
// ---------------------------------------------------------------------------
__global__ __launch_bounds__(256, 2) void gemm_final(
    const __half* __restrict__ ah, const __half* __restrict__ Yh, float* __restrict__ partial)
{
    extern __shared__ __half smem[];
    const int z = blockIdx.z;
    const __half* A = ah + (long long)(z & 3) * (16 * M1) + (long long)(z >> 2) * (2 * M1);
    const __half* B = Yh + (long long)(z & 3) * M1 + (long long)(z >> 2) * (8 * M1);
    gemm_body<false, true, false>(A, B, partial + (long long)z * M1, 1024, 1024, 1024, 2048, smem);
}

// ---------------------------------------------------------------------------
// Fused prep: one launch, 5 segments (256 threads).
// ---------------------------------------------------------------------------
__global__ __launch_bounds__(256) void prep_kernel(
    const float* __restrict__ x,  const float* __restrict__ Wq,
    const float* __restrict__ Wk, const float* __restrict__ Wv,
    const float* __restrict__ Wo,
    __half* __restrict__ xh, __half* __restrict__ wqT,
    __half* __restrict__ wkh, __half* __restrict__ wvT,
    __half* __restrict__ wog)
{
    const int blk = blockIdx.x;
    const int t = threadIdx.x;

    if (blk < 20480) {
        const float4* src; __half2* dst; int idx;
        if (blk < 4096) { src = (const float4*)x;  dst = (__half2*)xh;  idx = blk * 256 + t; }
        else            { src = (const float4*)Wk; dst = (__half2*)wkh; idx = (blk - 4096) * 256 + t; }
        const float4 v = src[idx];
        dst[2 * idx]     = __floats2half2_rn(v.x, v.y);
        dst[2 * idx + 1] = __floats2half2_rn(v.z, v.w);
    } else if (blk < 53248) {
        const float* src; __half* dst; int ti;
        if (blk < 36864) { src = Wq; dst = wqT; ti = blk - 20480; }
        else             { src = Wv; dst = wvT; ti = blk - 36864; }
        const int zh = ti >> 10;
        const int by = ((ti >> 5) & 31) * 32;
        const int bx = (ti & 31) * 32;
        const float* s = src + (long long)zh * 1048576;
        __half* d = dst + (long long)zh * 1048576;
        __shared__ float tt[32][33];
        const int tx = t & 31, ty = t >> 5;
#pragma unroll
        for (int i = 0; i < 4; i++)
            tt[ty + i * 8][tx] = s[(long long)(by + ty + i * 8) * 1024 + bx + tx];
        __syncthreads();
#pragma unroll
        for (int i = 0; i < 4; i++)
            d[(long long)(bx + ty + i * 8) * 1024 + by + tx] =
                __float2half_rn(tt[tx][ty + i * 8]);
    } else {
        const int idx = (blk - 53248) * 256 + t;
        const int o4 = idx & 255;
        const int dd = (idx >> 8) & 1023;
        const int h  = idx >> 18;
        const int srcRow = ((dd >> 6) * 16 + h) * 64 + (dd & 63);
        const float4 v = ((const float4*)Wo)[(long long)srcRow * 256 + o4];
        __half2* dst = (__half2*)wog;
        dst[2 * idx]     = __floats2half2_rn(v.x, v.y);
        dst[2 * idx + 1] = __floats2half2_rn(v.z, v.w);
    }
}

// ---------------------------------------------------------------------------
// In-place masked softmax (vectorized); also emits half copy for the final GEMM.
// ---------------------------------------------------------------------------
__global__ __launch_bounds__(256) void softmax_kernel(
    float* __restrict__ attn, __half* __restrict__ attnh, const float* __restrict__ mask)
{
    const int row = blockIdx.x;          // 0 .. 65535
    const int b = row >> 14;
    const int l = row & 1023;
    float4* p4 = (float4*)(attn + (long long)row * 1024);
    __half2* ph2 = (__half2*)(attnh + (long long)row * 1024);
    const float4* m4 = (const float4*)(mask + ((long long)(b << 10) + l) * 1024);

    const int tid = threadIdx.x;
    float4 v = p4[tid];
    const float4 m = m4[tid];
    v.x = v.x * 0.03125f - 1e9f * m.x;
    v.y = v.y * 0.03125f - 1e9f * m.y;
    v.z = v.z * 0.03125f - 1e9f * m.z;
    v.w = v.w * 0.03125f - 1e9f * m.w;
    float mx = fmaxf(fmaxf(v.x, v.y), fmaxf(v.z, v.w));

    __shared__ float red[8];
#pragma unroll
    for (int o = 16; o; o >>= 1) mx = fmaxf(mx, __shfl_xor_sync(0xffffffffu, mx, o));
    if ((tid & 31) == 0) red[tid >> 5] = mx;
    __syncthreads();
    mx = red[0];
#pragma unroll
    for (int w = 1; w < 8; w++) mx = fmaxf(mx, red[w]);
    __syncthreads();

    v.x = __expf(v.x - mx);
    v.y = __expf(v.y - mx);
    v.z = __expf(v.z - mx);
    v.w = __expf(v.w - mx);
    float s = v.x + v.y + v.z + v.w;
#pragma unroll
    for (int o = 16; o; o >>= 1) s += __shfl_xor_sync(0xffffffffu, s, o);
    if ((tid & 31) == 0) red[tid >> 5] = s;
    __syncthreads();
    s = red[0];
#pragma unroll
    for (int w = 1; w < 8; w++) s += red[w];
    const float inv = 1.0f / s;

    v.x *= inv; v.y *= inv; v.z *= inv; v.w *= inv;
    p4[tid] = v;
    ph2[2 * tid]     = __floats2half2_rn(v.x, v.y);
    ph2[2 * tid + 1] = __floats2half2_rn(v.z, v.w);
}

// ---------------------------------------------------------------------------
// Split-K reduce: out[i] = sum of 8 partials (each 4M floats).
// ---------------------------------------------------------------------------
__global__ __launch_bounds__(256) void reduce8_kernel(
    const float4* __restrict__ part, float4* __restrict__ out)
{
    const int i = blockIdx.x * 256 + threadIdx.x;   // < 1M float4
    float4 a = part[i];
#pragma unroll
    for (int c = 1; c < 8; c++) {
        const float4 b = part[i + c * 1048576];
        a.x += b.x; a.y += b.y; a.z += b.z; a.w += b.w;
    }
    out[i] = a;
}

// ---------------------------------------------------------------------------
extern "C" void kernel_launch(void* const* d_in, const int* in_sizes, int n_in,
                              void* d_out, int out_size)
{
    const float* x    = (const float*)d_in[0];
    const float* mask = (const float*)d_in[1];
    const float* Wq   = (const float*)d_in[2];
    const float* Wk   = (const float*)d_in[3];
    const float* Wv   = (const float*)d_in[4];
    const float* Wo   = (const float*)d_in[5];
    float* out  = (float*)d_out;
    float* attn = out + 4LL * 1024 * 1024;

    __half *xh, *wkh, *wqT, *wvT, *wog, *Gh, *Uh, *Ph, *Yh, *ah;
    cudaGetSymbolAddress((void**)&xh,  h_x);
    cudaGetSymbolAddress((void**)&wkh, h_wk);
    cudaGetSymbolAddress((void**)&wqT, h_wqT);
    cudaGetSymbolAddress((void**)&wvT, h_wvT);
    cudaGetSymbolAddress((void**)&wog, h_wog);
    cudaGetSymbolAddress((void**)&Gh,  h_G);
    cudaGetSymbolAddress((void**)&Uh,  h_U);
    cudaGetSymbolAddress((void**)&Ph,  h_P);
    cudaGetSymbolAddress((void**)&Yh,  h_Y);
    cudaGetSymbolAddress((void**)&ah,  h_attn);
    float* partial = (float*)Ph;   // reuse h_P after logits GEMM (exactly 128 MB)

    cudaFuncSetAttribute((const void*)gemm_gu,
                         cudaFuncAttributeMaxDynamicSharedMemorySize, SMEM_BYTES);
    cudaFuncSetAttribute((const void*)gemm_p,
                         cudaFuncAttributeMaxDynamicSharedMemorySize, SMEM_BYTES);
    cudaFuncSetAttribute((const void*)gemm_ly,
                         cudaFuncAttributeMaxDynamicSharedMemorySize, SMEM_BYTES);
    cudaFuncSetAttribute((const void*)gemm_final,
                         cudaFuncAttributeMaxDynamicSharedMemorySize, SMEM_BYTES);

    const dim3 blk(256);

    // 0) fused prep (x, Wk convert; Wq, Wv transpose; Wo gather)
    prep_kernel<<<69632, 256>>>(x, Wq, Wk, Wv, Wo, xh, wqT, wkh, wvT, wog);

    // 1) merged G+U  (z 0..31)
    gemm_gu<<<dim3(8, 8, 32), blk, SMEM_BYTES>>>(wqT, wkh, wvT, wog, Gh, Uh);

    // 2) P = x @ G_h  (z 0..15)
    gemm_p<<<dim3(8, 32, 16), blk, SMEM_BYTES>>>(xh, Gh, Ph);

    // 3) merged logits (z 0..63) + Y (z 64..127)
    gemm_ly<<<dim3(8, 8, 128), blk, SMEM_BYTES>>>(Ph, xh, Uh, attn, Yh);

    // 4) masked softmax in place (scale 1/32) + half copy
    softmax_kernel<<<65536, 256>>>(attn, ah, mask);

    // 5) split-K final, 8 chunks (z 0..31)
    gemm_final<<<dim3(8, 8, 32), blk, SMEM_BYTES>>>(ah, Yh, partial);

    // 6) reduce partials -> out
    reduce8_kernel<<<4096, 256>>>((const float4*)partial, (float4*)out);
}

// round 15
// speedup vs baseline: 1.0153x; 1.0080x over previous
#include <cuda_runtime.h>
#include <cstdint>
#include <cuda_fp16.h>
#include <mma.h>

using namespace nvcuda;

// Problem constants: B=4, L=1024, D=1024, H=16
// Half scratch buffers.
__device__ __half h_x[4194304];      // x [4096,1024]
__device__ __half h_wk[16777216];    // Wk [16,1024,1024]
__device__ __half h_wqT[16777216];   // Wq^T per head [16][i][d]
__device__ __half h_wvT[16777216];   // Wv^T per head [16][e][d]
__device__ __half h_wog[16777216];   // gathered Wo: [16][d][o]
__device__ __half h_G[16777216];     // G_h = Wq_h^T Wk_h
__device__ __half h_P[67108864];     // P = x @ G ; later reused as float[8][4M] split-K partials
__device__ __half h_U[16777216];     // U_h = Wv_h^T Wo'_h
__device__ __half h_Y[67108864];     // Y = x_b @ U_h  [(h*4+b)][1024][1024]
__device__ __half h_attn[67108864];  // attn half copy [(b*16+h)][1024][1024]

// ---------------------------------------------------------------------------
constexpr int BM = 128, BN = 128, BK = 64;
constexpr int STG = 3;
constexpr int LDA_S = BK + 8;            // 72 halves
constexpr int LDB_S = BN + 8;            // 136 halves
constexpr int A_TILE = BM * LDA_S;
constexpr int BT_TILE = BN * LDA_S;
constexpr int STAGE_H = A_TILE + BT_TILE;           // 18432 halves
constexpr int SMEM_BYTES = STG * STAGE_H * 2;       // 110592 B
constexpr long long M1 = 1024LL * 1024;
constexpr long long M4 = 4096LL * 1024;

__device__ __forceinline__ void cp16(const void* smem_dst, const void* src) {
    unsigned dst = (unsigned)__cvta_generic_to_shared(smem_dst);
    asm volatile("cp.async.cg.shared.global [%0], [%1], 16;\n" :: "r"(dst), "l"(src));
}
#define CP_COMMIT() asm volatile("cp.async.commit_group;" ::: "memory")
#define CP_WAIT(n)  asm volatile("cp.async.wait_group %0;" :: "n"(n) : "memory")

// ---------------------------------------------------------------------------
// fp16 wmma GEMM body, fp32 accumulate. 256 threads, 8 warps, 64x32 per warp.
//   BT   : C = A @ B^T (B stored [N,K]); else C = A @ B (B stored [K,N]).
//   SEGK : segmented-K (K split into 1024-row head segments, both strides 1024).
//   HOUT : half output via smem staging; else direct fp32 wmma store.
// A, Bp, Cc are fully batch-offset by the caller.
// ---------------------------------------------------------------------------
template <bool BT, bool SEGK, bool HOUT>
__device__ __forceinline__ void gemm_body(
    const __half* __restrict__ A, const __half* __restrict__ Bp,
    void* __restrict__ Cc, int lda, int ldb, int ldc, int K, __half* smem)
{
    __half* Asm = smem;
    __half* Bsm = smem + STG * A_TILE;

    const int tid = threadIdx.x;
    const int warpId = tid >> 5;
    const int lane = tid & 31;
    const int rowBase = blockIdx.y * BM;
    const int colBase = blockIdx.x * BN;
    const int wRow = (warpId >> 2) * 64;
    const int wCol = (warpId & 3) * 32;

    wmma::fragment<wmma::accumulator, 16, 16, 16, float> acc[4][2];
#pragma unroll
    for (int i = 0; i < 4; i++)
#pragma unroll
        for (int j = 0; j < 2; j++) wmma::fill_fragment(acc[i][j], 0.0f);

    const int T = K >> 6;

    auto a_base = [&](int kt) -> const __half* {
        const int k0 = kt << 6;
        if constexpr (SEGK) return A + ((long long)(k0 >> 10) << 20) + (k0 & 1023);
        else return A + k0;
    };
    auto b_base = [&](int kt) -> const __half* {
        const int k0 = kt << 6;
        if constexpr (SEGK) return Bp + ((long long)(k0 >> 10) << 22) + (long long)(k0 & 1023) * 1024;
        else return Bp + (BT ? k0 : (long long)k0 * ldb);
    };
    const int rs_a = SEGK ? 1024 : lda;
    const int rs_b = SEGK ? 1024 : ldb;

    auto issueA = [&](int kt) {
        const int buf = kt % STG;
        const __half* At = a_base(kt);
#pragma unroll
        for (int i = 0; i < 4; i++) {
            const int c = tid + i * 256;
            const int r = c >> 3;
            const int col = (c & 7) << 3;
            cp16(&Asm[(buf * BM + r) * LDA_S + col],
                 &At[(long long)(rowBase + r) * rs_a + col]);
        }
    };
    auto issueB = [&](int kt) {
        const int buf = kt % STG;
        const __half* Bt = b_base(kt);
        if constexpr (BT) {
#pragma unroll
            for (int i = 0; i < 4; i++) {
                const int c = tid + i * 256;
                const int r = c >> 3;
                const int col = (c & 7) << 3;
                cp16(&Bsm[(buf * BN + r) * LDA_S + col],
                     &Bt[(long long)(colBase + r) * rs_b + col]);
            }
        } else {
#pragma unroll
            for (int i = 0; i < 4; i++) {
                const int c = tid + i * 256;
                const int r = c >> 4;
                const int col = (c & 15) << 3;
                cp16(&Bsm[(buf * BK + r) * LDB_S + col],
                     &Bt[(long long)r * rs_b + colBase + col]);
            }
        }
    };

    // Reordered kk step: B fragments first, then per-i {load A; 2 MMAs}.
    auto compute = [&](const __half* Ab, const __half* Bb, int kk) {
        if constexpr (BT) {
            wmma::fragment<wmma::matrix_b, 16, 16, 16, __half, wmma::col_major> bf[2];
#pragma unroll
            for (int j = 0; j < 2; j++)
                wmma::load_matrix_sync(bf[j], &Bb[(wCol + j * 16) * LDA_S + kk], LDA_S);
#pragma unroll
            for (int i = 0; i < 4; i++) {
                wmma::fragment<wmma::matrix_a, 16, 16, 16, __half, wmma::row_major> af;
                wmma::load_matrix_sync(af, &Ab[(wRow + i * 16) * LDA_S + kk], LDA_S);
                wmma::mma_sync(acc[i][0], af, bf[0], acc[i][0]);
                wmma::mma_sync(acc[i][1], af, bf[1], acc[i][1]);
            }
        } else {
            wmma::fragment<wmma::matrix_b, 16, 16, 16, __half, wmma::row_major> bf[2];
#pragma unroll
            for (int j = 0; j < 2; j++)
                wmma::load_matrix_sync(bf[j], &Bb[kk * LDB_S + wCol + j * 16], LDB_S);
#pragma unroll
            for (int i = 0; i < 4; i++) {
                wmma::fragment<wmma::matrix_a, 16, 16, 16, __half, wmma::row_major> af;
                wmma::load_matrix_sync(af, &Ab[(wRow + i * 16) * LDA_S + kk], LDA_S);
                wmma::mma_sync(acc[i][0], af, bf[0], acc[i][0]);
                wmma::mma_sync(acc[i][1], af, bf[1], acc[i][1]);
            }
        }
    };

#pragma unroll
    for (int s = 0; s < STG - 1; s++) { issueA(s); issueB(s); CP_COMMIT(); }

    for (int kt = 0; kt < T; kt++) {
        // One barrier per tile: after wait+barrier, tile kt is visible to all and
        // all warps finished compute(kt-1) so its stage can be overwritten.
        CP_WAIT(STG - 2);
        __syncthreads();

        const int buf = kt % STG;
        const __half* Ab = &Asm[buf * BM * LDA_S];
        const __half* Bb = BT ? &Bsm[buf * BN * LDA_S] : &Bsm[buf * BK * LDB_S];

        // Spread the prefetch: A burst after kk=0, B burst after kk=16.
        // Still exactly one commit group per tile.  (R12 optimum.)
        const int pf = kt + STG - 1;
        compute(Ab, Bb, 0);
        if (pf < T) issueA(pf);
        compute(Ab, Bb, 16);
        if (pf < T) issueB(pf);
        CP_COMMIT();
        compute(Ab, Bb, 32);
        compute(Ab, Bb, 48);
    }

    if constexpr (!HOUT) {
        float* C = (float*)Cc;
#pragma unroll
        for (int i = 0; i < 4; i++)
#pragma unroll
            for (int j = 0; j < 2; j++) {
                float* cp = &C[(long long)(rowBase + wRow + i * 16) * ldc + colBase + wCol + j * 16];
                wmma::store_matrix_sync(cp, acc[i][j], ldc, wmma::mem_row_major);
            }
    } else {
        __syncthreads();
        float* patch = (float*)smem + warpId * 320;     // 16 x 20
        const int pr = lane & 15;
        const int ps = (lane >> 4) << 3;
#pragma unroll
        for (int i = 0; i < 4; i++)
#pragma unroll
            for (int j = 0; j < 2; j++) {
                wmma::store_matrix_sync(patch, acc[i][j], 20, wmma::mem_row_major);
                __syncwarp();
                union { uint4 u; __half2 hh[4]; } pk;
#pragma unroll
                for (int t = 0; t < 4; t++)
                    pk.hh[t] = __floats2half2_rn(patch[pr * 20 + ps + t * 2],
                                                 patch[pr * 20 + ps + t * 2 + 1]);
                const int row = rowBase + wRow + i * 16 + pr;
                const int col = colBase + wCol + j * 16;
                __half* dst = (__half*)Cc + (long long)row * ldc + col + ps;
                *reinterpret_cast<uint4*>(dst) = pk.u;
                __syncwarp();
            }
    }
}

// ---------------------------------------------------------------------------
// Merged G+U kernel: z<16 -> G_h = Wq_h^T @ Wk_h ; z>=16 -> U_h = Wv_h^T @ Wo'_h
// ---------------------------------------------------------------------------
__global__ __launch_bounds__(256, 2) void gemm_gu(
    const __half* __restrict__ wqT, const __half* __restrict__ wkh,
    const __half* __restrict__ wvT, const __half* __restrict__ wog,
    __half* __restrict__ G, __half* __restrict__ U)
{
    extern __shared__ __half smem[];
    const int z = blockIdx.z;
    const __half *A, *B;
    __half* C;
    if (z < 16) { A = wqT + (long long)z * M1; B = wkh + (long long)z * M1; C = G + (long long)z * M1; }
    else { const int y = z - 16; A = wvT + (long long)y * M1; B = wog + (long long)y * M1; C = U + (long long)y * M1; }
    gemm_body<false, false, true>(A, B, C, 1024, 1024, 1024, 1024, smem);
}

// ---------------------------------------------------------------------------
// P = x @ G_h  (per head z)
// ---------------------------------------------------------------------------
__global__ __launch_bounds__(256, 2) void gemm_p(
    const __half* __restrict__ xh, const __half* __restrict__ G, __half* __restrict__ P)
{
    extern __shared__ __half smem[];
    const int z = blockIdx.z;
    gemm_body<false, false, true>(xh, G + (long long)z * M1, P + (long long)z * M4,
                                  1024, 1024, 1024, 1024, smem);
}

// ---------------------------------------------------------------------------
// Merged logits+Y kernel:
//   z<64 : logits = P_{h,b} @ x_b^T (BT, fp32 store at plane zp=(z&3)*16+(z>>2))
//   z>=64: Y_{h,b} = x_b @ U_h (NN, half out), y=z-64, y=h*4+b
// ---------------------------------------------------------------------------
__global__ __launch_bounds__(256, 2) void gemm_ly(
    const __half* __restrict__ Ph, const __half* __restrict__ xh,
    const __half* __restrict__ Uh, float* __restrict__ attn, __half* __restrict__ Yh)
{
    extern __shared__ __half smem[];
    const int z = blockIdx.z;
    if (z < 64) {
        const int zp = (z & 3) * 16 + (z >> 2);
        gemm_body<true, false, false>(Ph + (long long)z * M1, xh + (long long)(z & 3) * M1,
                                      attn + (long long)zp * M1, 1024, 1024, 1024, 1024, smem);
    } else {
        const int y = z - 64;
        gemm_body<false, false, true>(xh + (long long)(y & 3) * M1, Uh + (long long)(y >> 2) * M1,
                                      Yh + (long long)y * M1, 1024, 1024, 1024, 1024, smem);
    }
}

// ---------------------------------------------------------------------------
// Split-K final (8 chunks): z = c*4+b, c=z>>2 covers heads {2c, 2c+1}, b=z&3.
//   partial[z] = attn_{heads 2c..2c+1, b} @ Y_{...}  (segmented K=2048)
// ---------------------------------------------------------------------------
__global__ __launch_bounds__(256, 2) void gemm_final(
    const __half* __restrict__ ah, const __half* __restrict__ Yh, float* __restrict__ partial)
{
    extern __shared__ __half smem[];
    const int z = blockIdx.z;
    const __half* A = ah + (long long)(z & 3) * (16 * M1) + (long long)(z >> 2) * (2 * M1);
    const __half* B = Yh + (long long)(z & 3) * M1 + (long long)(z >> 2) * (8 * M1);
    gemm_body<false, true, false>(A, B, partial + (long long)z * M1, 1024, 1024, 1024, 2048, smem);
}

// ---------------------------------------------------------------------------
// Fused prep: one launch, 5 segments (256 threads).
// ---------------------------------------------------------------------------
__global__ __launch_bounds__(256) void prep_kernel(
    const float* __restrict__ x,  const float* __restrict__ Wq,
    const float* __restrict__ Wk, const float* __restrict__ Wv,
    const float* __restrict__ Wo,
    __half* __restrict__ xh, __half* __restrict__ wqT,
    __half* __restrict__ wkh, __half* __restrict__ wvT,
    __half* __restrict__ wog)
{
    const int blk = blockIdx.x;
    const int t = threadIdx.x;

    if (blk < 20480) {
        const float4* src; __half2* dst; int idx;
        if (blk < 4096) { src = (const float4*)x;  dst = (__half2*)xh;  idx = blk * 256 + t; }
        else            { src = (const float4*)Wk; dst = (__half2*)wkh; idx = (blk - 4096) * 256 + t; }
        const float4 v = src[idx];
        dst[2 * idx]     = __floats2half2_rn(v.x, v.y);
        dst[2 * idx + 1] = __floats2half2_rn(v.z, v.w);
    } else if (blk < 53248) {
        const float* src; __half* dst; int ti;
        if (blk < 36864) { src = Wq; dst = wqT; ti = blk - 20480; }
        else             { src = Wv; dst = wvT; ti = blk - 36864; }
        const int zh = ti >> 10;
        const int by = ((ti >> 5) & 31) * 32;
        const int bx = (ti & 31) * 32;
        const float* s = src + (long long)zh * 1048576;
        __half* d = dst + (long long)zh * 1048576;
        __shared__ float tt[32][33];
        const int tx = t & 31, ty = t >> 5;
#pragma unroll
        for (int i = 0; i < 4; i++)
            tt[ty + i * 8][tx] = s[(long long)(by + ty + i * 8) * 1024 + bx + tx];
        __syncthreads();
#pragma unroll
        for (int i = 0; i < 4; i++)
            d[(long long)(bx + ty + i * 8) * 1024 + by + tx] =
                __float2half_rn(tt[tx][ty + i * 8]);
    } else {
        const int idx = (blk - 53248) * 256 + t;
        const int o4 = idx & 255;
        const int dd = (idx >> 8) & 1023;
        const int h  = idx >> 18;
        const int srcRow = ((dd >> 6) * 16 + h) * 64 + (dd & 63);
        const float4 v = ((const float4*)Wo)[(long long)srcRow * 256 + o4];
        __half2* dst = (__half2*)wog;
        dst[2 * idx]     = __floats2half2_rn(v.x, v.y);
        dst[2 * idx + 1] = __floats2half2_rn(v.z, v.w);
    }
}

// ---------------------------------------------------------------------------
// In-place masked softmax (vectorized); also emits half copy for the final GEMM.
// ---------------------------------------------------------------------------
__global__ __launch_bounds__(256) void softmax_kernel(
    float* __restrict__ attn, __half* __restrict__ attnh, const float* __restrict__ mask)
{
    const int row = blockIdx.x;          // 0 .. 65535
    const int b = row >> 14;
    const int l = row & 1023;
    float4* p4 = (float4*)(attn + (long long)row * 1024);
    __half2* ph2 = (__half2*)(attnh + (long long)row * 1024);
    const float4* m4 = (const float4*)(mask + ((long long)(b << 10) + l) * 1024);

    const int tid = threadIdx.x;
    float4 v = p4[tid];
    const float4 m = m4[tid];
    v.x = v.x * 0.03125f - 1e9f * m.x;
    v.y = v.y * 0.03125f - 1e9f * m.y;
    v.z = v.z * 0.03125f - 1e9f * m.z;
    v.w = v.w * 0.03125f - 1e9f * m.w;
    float mx = fmaxf(fmaxf(v.x, v.y), fmaxf(v.z, v.w));

    __shared__ float red[8];
#pragma unroll
    for (int o = 16; o; o >>= 1) mx = fmaxf(mx, __shfl_xor_sync(0xffffffffu, mx, o));
    if ((tid & 31) == 0) red[tid >> 5] = mx;
    __syncthreads();
    mx = red[0];
#pragma unroll
    for (int w = 1; w < 8; w++) mx = fmaxf(mx, red[w]);
    __syncthreads();

    v.x = __expf(v.x - mx);
    v.y = __expf(v.y - mx);
    v.z = __expf(v.z - mx);
    v.w = __expf(v.w - mx);
    float s = v.x + v.y + v.z + v.w;
#pragma unroll
    for (int o = 16; o; o >>= 1) s += __shfl_xor_sync(0xffffffffu, s, o);
    if ((tid & 31) == 0) red[tid >> 5] = s;
    __syncthreads();
    s = red[0];
#pragma unroll
    for (int w = 1; w < 8; w++) s += red[w];
    const float inv = 1.0f / s;

    v.x *= inv; v.y *= inv; v.z *= inv; v.w *= inv;
    p4[tid] = v;
    ph2[2 * tid]     = __floats2half2_rn(v.x, v.y);
    ph2[2 * tid + 1] = __floats2half2_rn(v.z, v.w);
}

// ---------------------------------------------------------------------------
// Split-K reduce: out[i] = sum of 8 partials (each 4M floats).
// ---------------------------------------------------------------------------
__global__ __launch_bounds__(256) void reduce8_kernel(
    const float4* __restrict__ part, float4* __restrict__ out)
{
    const int i = blockIdx.x * 256 + threadIdx.x;   // < 1M float4
    float4 a = part[i];
#pragma unroll
    for (int c = 1; c < 8; c++) {
        const float4 b = part[i + c * 1048576];
        a.x += b.x; a.y += b.y; a.z += b.z; a.w += b.w;
    }
    out[i] = a;
}

// ---------------------------------------------------------------------------
extern "C" void kernel_launch(void* const* d_in, const int* in_sizes, int n_in,
                              void* d_out, int out_size)
{
    const float* x    = (const float*)d_in[0];
    const float* mask = (const float*)d_in[1];
    const float* Wq   = (const float*)d_in[2];
    const float* Wk   = (const float*)d_in[3];
    const float* Wv   = (const float*)d_in[4];
    const float* Wo   = (const float*)d_in[5];
    float* out  = (float*)d_out;
    float* attn = out + 4LL * 1024 * 1024;

    __half *xh, *wkh, *wqT, *wvT, *wog, *Gh, *Uh, *Ph, *Yh, *ah;
    cudaGetSymbolAddress((void**)&xh,  h_x);
    cudaGetSymbolAddress((void**)&wkh, h_wk);
    cudaGetSymbolAddress((void**)&wqT, h_wqT);
    cudaGetSymbolAddress((void**)&wvT, h_wvT);
    cudaGetSymbolAddress((void**)&wog, h_wog);
    cudaGetSymbolAddress((void**)&Gh,  h_G);
    cudaGetSymbolAddress((void**)&Uh,  h_U);
    cudaGetSymbolAddress((void**)&Ph,  h_P);
    cudaGetSymbolAddress((void**)&Yh,  h_Y);
    cudaGetSymbolAddress((void**)&ah,  h_attn);
    float* partial = (float*)Ph;   // reuse h_P after logits GEMM (exactly 128 MB)

    cudaFuncSetAttribute((const void*)gemm_gu,
                         cudaFuncAttributeMaxDynamicSharedMemorySize, SMEM_BYTES);
    cudaFuncSetAttribute((const void*)gemm_p,
                         cudaFuncAttributeMaxDynamicSharedMemorySize, SMEM_BYTES);
    cudaFuncSetAttribute((const void*)gemm_ly,
                         cudaFuncAttributeMaxDynamicSharedMemorySize, SMEM_BYTES);
    cudaFuncSetAttribute((const void*)gemm_final,
                         cudaFuncAttributeMaxDynamicSharedMemorySize, SMEM_BYTES);

    const dim3 blk(256);

    // 0) fused prep (x, Wk convert; Wq, Wv transpose; Wo gather)
    prep_kernel<<<69632, 256>>>(x, Wq, Wk, Wv, Wo, xh, wqT, wkh, wvT, wog);

    // 1) merged G+U  (z 0..31)
    gemm_gu<<<dim3(8, 8, 32), blk, SMEM_BYTES>>>(wqT, wkh, wvT, wog, Gh, Uh);

    // 2) P = x @ G_h  (z 0..15)
    gemm_p<<<dim3(8, 32, 16), blk, SMEM_BYTES>>>(xh, Gh, Ph);

    // 3) merged logits (z 0..63) + Y (z 64..127)
    gemm_ly<<<dim3(8, 8, 128), blk, SMEM_BYTES>>>(Ph, xh, Uh, attn, Yh);

    // 4) masked softmax in place (scale 1/32) + half copy
    softmax_kernel<<<65536, 256>>>(attn, ah, mask);

    // 5) split-K final, 8 chunks (z 0..31)
    gemm_final<<<dim3(8, 8, 32), blk, SMEM_BYTES>>>(ah, Yh, partial);

    // 6) reduce partials -> out
    reduce8_kernel<<<4096, 256>>>((const float4*)partial, (float4*)out);
}